// round 15
// baseline (speedup 1.0000x reference)
#include <cuda_runtime.h>

// Problem constants (fixed by the dataset: node_idx=28, P=320, D=3, sigma=10)
#define NNODE 28
#define PPT   320
#define NPTS  (NNODE * PPT)   // 8960 points per tensor
#define MID   13              // (node_idx-2)/2
#define SIGMA 10.0f

#define HALF_B   160                     // B half-tile size
#define NHB      (2 * NNODE)             // 56 half-rows
#define PAIR_TILES   (14 * NHB * 2)      // 1568
#define NBLOCKS      (148 * 8)           // 1184 = one full wave at 8 blocks/SM
#define STATS_BLOCKS (2 * NPTS / 160)    // 112

typedef unsigned long long u64;

// Scratch (no allocations allowed -> device globals)
// g_M[dir][hb * NPTS + pt], hb = 2*node + half : d/2 = aw + min(bw - a.b)
__device__ float g_M[2][NHB * NPTS];       // 4 MB
__device__ float g_part[STATS_BLOCKS];
__device__ int   g_tile;                   // next pair tile (reset by last stats block)
__device__ int   g_done;                   // blocks past the work loop
__device__ int   g_cnt;                    // stats blocks finished

// ---------------------------------------------------------------------------
// Packed f32x2 helpers (Blackwell sm_100+). No packed min exists; mov.b64
// unpack maps to register-pair halves and is elided by ptxas.
// ---------------------------------------------------------------------------
__device__ __forceinline__ u64 pack2(float lo, float hi) {
    u64 r;
    asm("mov.b64 %0, {%1, %2};" : "=l"(r) : "f"(lo), "f"(hi));
    return r;
}
__device__ __forceinline__ u64 fma2(u64 a, u64 b, u64 c) {
    u64 d;
    asm("fma.rn.f32x2 %0, %1, %2, %3;" : "=l"(d) : "l"(a), "l"(b), "l"(c));
    return d;
}
__device__ __forceinline__ void unpack2(u64 v, float& lo, float& hi) {
    asm("mov.b64 {%0, %1}, %2;" : "=f"(lo), "=f"(hi) : "l"(v));
}
__device__ __forceinline__ float clipf(float v) {
    return fminf(fmaxf(v, -SIGMA), SIGMA);
}

// ---------------------------------------------------------------------------
// Persistent fused kernel, grid = exactly one wave (1184 blocks x 160 thr).
// Phase 1: dynamic tile stealing over the 1568 pair tiles (R5's proven body:
// 2 A nodes x 4 A pts/thread vs one B half-tile in smem, broadcast LDS,
// 4 independent fma2 chains, aw added at store). Self-balancing: ~10.6 tiles
// per SM, no straggler wave.
// Phase 2: software barrier; blocks 0..111 compute the per-point closed-form
// stats + deterministic fused final sum. Last stats block resets counters.
// ---------------------------------------------------------------------------
__global__ __launch_bounds__(160, 8) void fused_kernel(const float* __restrict__ X,
                                                       const float* __restrict__ T,
                                                       float* __restrict__ out) {
    const int t = threadIdx.x;

    __shared__ ulonglong2 sXY[HALF_B / 2];
    __shared__ ulonglong2 sZW[HALF_B / 2];
    __shared__ int s_tile;

    // ----------------- phase 1: pair tiles (work stealing) -----------------
    for (;;) {
        if (t == 0) s_tile = atomicAdd(&g_tile, 1);
        __syncthreads();                    // tile bcast; also protects smem reuse
        const int tile = s_tile;
        if (tile >= PAIR_TILES) break;

        const int dir = tile & 1;
        const int r = tile >> 1;            // 0..783
        const int bx = r % 14;              // A stripe (2 nodes)
        const int hb = r / 14;              // B half-tile 0..55

        const float* __restrict__ Araw = dir ? T : X;
        const float* __restrict__ Braw = dir ? X : T;

        // Fill + clip B half-tile (one point per thread)
        {
            const int node = hb >> 1, half = hb & 1;
            const float* bsrc = Braw + ((size_t)node * PPT + half * HALF_B) * 3;
            float x = clipf(bsrc[3 * t + 0]);
            float y = clipf(bsrc[3 * t + 1]);
            float z = clipf(bsrc[3 * t + 2]);
            float w = fmaf(0.5f * x, x, fmaf(0.5f * y, y, 0.5f * z * z));
            float* fXY = reinterpret_cast<float*>(sXY);
            float* fZW = reinterpret_cast<float*>(sZW);
            int q = t >> 1, rr = t & 1;
            fXY[q * 4 + 0 + rr] = x;
            fXY[q * 4 + 2 + rr] = y;
            fZW[q * 4 + 0 + rr] = z;
            fZW[q * 4 + 2 + rr] = w;
        }
        __syncthreads();

        // Load + clip 4 A points (2 nodes: base point = bx*640)
        const int aBase = bx * (2 * PPT);
        const float* asrc = Araw + (size_t)aBase * 3;
        u64 nax[4], nay[4], naz[4];
        float aw[4];
#pragma unroll
        for (int k = 0; k < 4; k++) {
            int j = t + k * 160;
            float x = clipf(asrc[3 * j + 0]);
            float y = clipf(asrc[3 * j + 1]);
            float z = clipf(asrc[3 * j + 2]);
            aw[k] = fmaf(0.5f * x, x, fmaf(0.5f * y, y, 0.5f * z * z));
            nax[k] = pack2(-x, -x);
            nay[k] = pack2(-y, -y);
            naz[k] = pack2(-z, -z);
        }

        float m[4];
#pragma unroll
        for (int k = 0; k < 4; k++) m[k] = 3.0e38f;

#pragma unroll 2
        for (int q = 0; q < HALF_B / 2; q++) {
            ulonglong2 bxy = sXY[q];   // packed x pair, y pair (broadcast LDS)
            ulonglong2 bzw = sZW[q];   // packed z pair, bw pair
#pragma unroll
            for (int k = 0; k < 4; k++) {
                u64 f = fma2(naz[k], bzw.x, bzw.y);
                f = fma2(nay[k], bxy.y, f);
                f = fma2(nax[k], bxy.x, f);
                float lo, hi;
                unpack2(f, lo, hi);          // register-pair alias: no SASS cost
                m[k] = fminf(m[k], fminf(lo, hi));
            }
        }

        // Coalesced store of d/2 mins
        float* __restrict__ Mrow = g_M[dir] + (size_t)hb * NPTS + aBase;
#pragma unroll
        for (int k = 0; k < 4; k++) Mrow[t + k * 160] = m[k] + aw[k];
    }

    // Signal: this block's g_M stores are globally visible
    __threadfence();
    __syncthreads();
    if (t == 0) atomicAdd(&g_done, 1);

    // ----------------- phase 2: stats (blocks 0..111) -----------------
    const int bid = blockIdx.x;
    if (bid >= STATS_BLOCKS) return;

    if (t == 0) {
        while (atomicAdd(&g_done, 0) < NBLOCKS) __nanosleep(64);
    }
    __syncthreads();
    __threadfence();                        // acquire all pair stores

    const int gp = bid * 160 + t;           // 0..17919
    const int dir = (gp >= NPTS) ? 1 : 0;
    const int p = gp - dir * NPTS;
    const int u = p / PPT;                  // node of this point
    const float* __restrict__ Md = g_M[dir] + p;

    // Per point: min m @ argmin a, second-min s2, half-range min h over the
    // 28 per-node d/2 mins (each = min of two half rows).
    float m = 3.0e38f, s2 = 3.0e38f, h = 3.0e38f;
    int a = -1;
    const int h0 = (u < MID) ? 0 : MID;
    const int h1 = (u < MID) ? MID : NNODE;
#pragma unroll
    for (int j = 0; j < NNODE; j++) {
        float f0 = Md[(size_t)(2 * j + 0) * NPTS];   // coalesced across warp
        float f1 = Md[(size_t)(2 * j + 1) * NPTS];
        float vj = fminf(f0, f1);
        if (vj < m) { s2 = m; m = vj; a = j; }
        else        { s2 = fminf(s2, vj); }
        if (j >= h0 && j < h1) h = fminf(h, vj);
    }

    // cf = 26*m + (a<=25 ? s2-m : 0) + [u<=25]*(v(e)-v(u)) + h ; contrib = 2*cf
    float cf = 26.0f * m + h;
    if (a <= NNODE - 3) cf += (s2 - m);
    if (u <= NNODE - 3) {
        int idx_e = (u < MID) ? (u + MID) : (u - MID);
        float v_u = (a == u)     ? s2 : m;
        float v_e = (a == idx_e) ? s2 : m;
        cf += v_e - v_u;
    }
    float contrib = 2.0f * cf;

    // Deterministic block reduction: warp butterflies, fixed-order 5-warp fold
    const int lane = t & 31;
    const int warp = t >> 5;
#pragma unroll
    for (int off = 16; off > 0; off >>= 1)
        contrib += __shfl_xor_sync(0xffffffffu, contrib, off);

    __shared__ float wsum[5];
    if (lane == 0) wsum[warp] = contrib;
    __syncthreads();

    if (warp == 0) {
        int last = 0;
        if (lane == 0) {
            float bs = ((wsum[0] + wsum[1]) + (wsum[2] + wsum[3])) + wsum[4];
            g_part[bid] = bs;
            __threadfence();
            last = (atomicAdd(&g_cnt, 1) == STATS_BLOCKS - 1);
        }
        last = __shfl_sync(0xffffffffu, last, 0);
        if (last) {
            __threadfence();                              // acquire all g_part
            float ssum = 0.0f;
            for (int i = lane; i < STATS_BLOCKS; i += 32) // fixed order per lane
                ssum += __ldcg(&g_part[i]);
#pragma unroll
            for (int off = 16; off > 0; off >>= 1)
                ssum += __shfl_xor_sync(0xffffffffu, ssum, off);
            if (lane == 0) {
                out[0] = ssum;
                g_tile = 0;                               // reset for next replay
                g_done = 0;
                g_cnt = 0;
            }
        }
    }
}

extern "C" void kernel_launch(void* const* d_in, const int* in_sizes, int n_in,
                              void* d_out, int out_size) {
    const float* X = (const float*)d_in[0];       // X_v        [28,320,3] f32
    const float* T = (const float*)d_in[1];       // target_X_v [28,320,3] f32
    (void)in_sizes; (void)n_in; (void)out_size;   // node_idx fixed at 28

    fused_kernel<<<NBLOCKS, 160>>>(X, T, (float*)d_out);
}

// round 16
// speedup vs baseline: 1.1429x; 1.1429x over previous
#include <cuda_runtime.h>

// Problem constants (fixed by the dataset: node_idx=28, P=320, D=3, sigma=10)
#define NNODE 28
#define PPT   320
#define NPTS  (NNODE * PPT)   // 8960 points per tensor
#define MID   13              // (node_idx-2)/2
#define SIGMA 10.0f

#define HALF_B   160                     // B half-tile size
#define NHB      (2 * NNODE)             // 56 half-rows
#define NQ       (HALF_B / 2)            // 80 q-iterations
#define STATS_THREADS 512
#define STATS_BLOCKS  (2 * NPTS / STATS_THREADS)   // 35

typedef unsigned long long u64;

// Scratch (no allocations allowed -> device globals)
// g_M[dir][hb * NPTS + pt], hb = 2*node + half : g = aw + min(b.w - a.b) = d/2
__device__ float g_M[2][NHB * NPTS];       // 4 MB
__device__ float g_part[STATS_BLOCKS];
__device__ int   g_cnt;

// ---------------------------------------------------------------------------
// Packed f32x2 helpers (Blackwell sm_100+). No packed min exists; mov.b64
// unpack maps to register-pair halves and is elided by ptxas.
// ---------------------------------------------------------------------------
__device__ __forceinline__ u64 pack2(float lo, float hi) {
    u64 r;
    asm("mov.b64 %0, {%1, %2};" : "=l"(r) : "f"(lo), "f"(hi));
    return r;
}
__device__ __forceinline__ u64 fma2(u64 a, u64 b, u64 c) {
    u64 d;
    asm("fma.rn.f32x2 %0, %1, %2, %3;" : "=l"(d) : "l"(a), "l"(b), "l"(c));
    return d;
}
__device__ __forceinline__ void unpack2(u64 v, float& lo, float& hi) {
    asm("mov.b64 {%0, %1}, %2;" : "=f"(lo), "=f"(hi) : "l"(v));
}
__device__ __forceinline__ float clipf(float v) {
    return fminf(fmaxf(v, -SIGMA), SIGMA);
}

// ---------------------------------------------------------------------------
// Kernel 1 (R5 config + SOFTWARE-PIPELINED B loads): per-point per-B-half min
// of g = a.w + (b.w - a.b), clip fused. Grid (14, 56, 2), 160 threads.
// blockIdx.x: 2 A nodes (4 A pts/thread), blockIdx.y: B half-tile (160 pts in
// smem, broadcast LDS), blockIdx.z: direction. The q-loop prefetches iteration
// q+1's packed B values into registers while computing iteration q, hiding the
// 29-cyc LDS latency (diagnosed short_scoreboard stall: fma pipe only ~40%
// fed). Smem padded to NQ+1 entries so the last prefetch is branch-free.
// SMEM: sXY[q] = { pack(x2q,x2q+1), pack(y2q,y2q+1) }, sZW likewise z/bw.
// ---------------------------------------------------------------------------
__global__ __launch_bounds__(160, 8) void pair_min_kernel(const float* __restrict__ X,
                                                          const float* __restrict__ T) {
    if (blockIdx.x == 0 && blockIdx.y == 0 && blockIdx.z == 0 && threadIdx.x == 0)
        g_cnt = 0;

    const int dir = blockIdx.z;
    const float* __restrict__ Araw = dir ? T : X;
    const float* __restrict__ Braw = dir ? X : T;

    __shared__ ulonglong2 sXY[NQ + 1];   // +1 pad: q=NQ-1 prefetch reads junk, unused
    __shared__ ulonglong2 sZW[NQ + 1];

    const int t = threadIdx.x;

    // Fill + clip B half-tile (one point per thread)
    {
        const int node = blockIdx.y >> 1, half = blockIdx.y & 1;
        const float* bsrc = Braw + ((size_t)node * PPT + half * HALF_B) * 3;
        float x = clipf(bsrc[3 * t + 0]);
        float y = clipf(bsrc[3 * t + 1]);
        float z = clipf(bsrc[3 * t + 2]);
        float w = fmaf(0.5f * x, x, fmaf(0.5f * y, y, 0.5f * z * z));
        float* fXY = reinterpret_cast<float*>(sXY);
        float* fZW = reinterpret_cast<float*>(sZW);
        int q = t >> 1, r = t & 1;
        fXY[q * 4 + 0 + r] = x;
        fXY[q * 4 + 2 + r] = y;
        fZW[q * 4 + 0 + r] = z;
        fZW[q * 4 + 2 + r] = w;
    }
    __syncthreads();

    // Load + clip 4 A points (2 nodes: base point = blockIdx.x*640)
    const int aBase = blockIdx.x * (2 * PPT);
    const float* asrc = Araw + (size_t)aBase * 3;
    u64 nax[4], nay[4], naz[4];
    float aw[4];
#pragma unroll
    for (int k = 0; k < 4; k++) {
        int j = t + k * 160;
        float x = clipf(asrc[3 * j + 0]);
        float y = clipf(asrc[3 * j + 1]);
        float z = clipf(asrc[3 * j + 2]);
        aw[k] = fmaf(0.5f * x, x, fmaf(0.5f * y, y, 0.5f * z * z));
        nax[k] = pack2(-x, -x);
        nay[k] = pack2(-y, -y);
        naz[k] = pack2(-z, -z);
    }

    float m[4];
#pragma unroll
    for (int k = 0; k < 4; k++) m[k] = 3.0e38f;

    // Software pipeline: registers hold iteration q's B values; prefetch q+1
    ulonglong2 bxy = sXY[0];
    ulonglong2 bzw = sZW[0];

#pragma unroll 2
    for (int q = 0; q < NQ; q++) {
        ulonglong2 cxy = bxy;      // current iteration's packed x/y pairs
        ulonglong2 czw = bzw;      // current iteration's packed z/bw pairs
        bxy = sXY[q + 1];          // prefetch next (pad entry at q=NQ-1)
        bzw = sZW[q + 1];
#pragma unroll
        for (int k = 0; k < 4; k++) {
            u64 f = fma2(naz[k], czw.x, czw.y);
            f = fma2(nay[k], cxy.y, f);
            f = fma2(nax[k], cxy.x, f);
            float lo, hi;
            unpack2(f, lo, hi);              // register-pair alias: no SASS cost
            m[k] = fminf(m[k], fminf(lo, hi));
        }
    }

    // Epilogue: coalesced store of aw-shifted mins (= d/2)
    float* __restrict__ Mrow = g_M[dir] + (size_t)blockIdx.y * NPTS + aBase;
#pragma unroll
    for (int k = 0; k < 4; k++) Mrow[t + k * 160] = m[k] + aw[k];
}

// ---------------------------------------------------------------------------
// Kernel 2 (R5's exact proven shape: 35 blocks x 512, smem tree): per-point
// closed-form contribution. Per point in node u with per-node mins v[0..27]
// (folded from half rows), min m @ argmin a, second-min s, half-range min h:
//   cf = 26*m + (a<=25 ? s-m : 0) + [u<=25]*(v(e)-v(u)) + h ;  contrib = 2*cf
// Final sum fused via last-arriving block (fixed-order, deterministic).
// ---------------------------------------------------------------------------
__global__ __launch_bounds__(STATS_THREADS) void stats_kernel(float* __restrict__ out) {
    int gp = blockIdx.x * STATS_THREADS + threadIdx.x;   // 0 .. 17919
    int dir = (gp >= NPTS) ? 1 : 0;
    int p = gp - dir * NPTS;
    int u = p / PPT;                                     // node of this point
    const float* __restrict__ Md = g_M[dir];

    float m = 3.0e38f, s = 3.0e38f, h = 3.0e38f;
    int a = -1;
    const int h0 = (u < MID) ? 0 : MID;
    const int h1 = (u < MID) ? MID : NNODE;
#pragma unroll
    for (int j = 0; j < NNODE; j++) {
        float f0 = Md[(size_t)(2 * j + 0) * NPTS + p];   // coalesced
        float f1 = Md[(size_t)(2 * j + 1) * NPTS + p];
        float vj = fminf(f0, f1);
        if (vj < m) { s = m; m = vj; a = j; }
        else        { s = fminf(s, vj); }
        if (j >= h0 && j < h1) h = fminf(h, vj);
    }

    float cf = 26.0f * m + h;
    if (a <= NNODE - 3) cf += (s - m);                   // a in 0..25
    if (u <= NNODE - 3) {                                // u in 0..25
        int idx_e = (u < MID) ? (u + MID) : (u - MID);
        float v_u = (a == u)     ? s : m;
        float v_e = (a == idx_e) ? s : m;
        cf += v_e - v_u;
    }
    float contrib = 2.0f * cf;

    __shared__ float red[STATS_THREADS];
    red[threadIdx.x] = contrib;
    __syncthreads();
#pragma unroll
    for (int off = STATS_THREADS / 2; off > 0; off >>= 1) {
        if (threadIdx.x < off) red[threadIdx.x] += red[threadIdx.x + off];
        __syncthreads();
    }

    if (threadIdx.x == 0) {
        g_part[blockIdx.x] = red[0];
        __threadfence();
        int old = atomicAdd(&g_cnt, 1);
        if (old == STATS_BLOCKS - 1) {                   // last block: all parts visible
            float ssum = 0.0f;
#pragma unroll
            for (int i = 0; i < STATS_BLOCKS; i++) ssum += g_part[i];
            out[0] = ssum;
        }
    }
}

extern "C" void kernel_launch(void* const* d_in, const int* in_sizes, int n_in,
                              void* d_out, int out_size) {
    const float* X = (const float*)d_in[0];       // X_v        [28,320,3] f32
    const float* T = (const float*)d_in[1];       // target_X_v [28,320,3] f32
    (void)in_sizes; (void)n_in; (void)out_size;   // node_idx fixed at 28

    dim3 g1(NNODE / 2, NHB, 2);                   // (14, 56, 2)
    pair_min_kernel<<<g1, 160>>>(X, T);

    stats_kernel<<<STATS_BLOCKS, STATS_THREADS>>>((float*)d_out);
}